// round 7
// baseline (speedup 1.0000x reference)
#include <cuda_runtime.h>
#include <math.h>

// Naive, correctness-first implementation. Every stage is a direct
// transcription of the reference math. One thread per output element.

__device__ float g_Q[512 * 192];
__device__ float g_K[512 * 192];
__device__ float g_V[512 * 192];
__device__ float g_QP[512 * 144];
__device__ float g_KP[512 * 144];
__device__ float g_VP[512 * 288];
__device__ float g_QG[512 * 144];
__device__ float g_KG[512 * 144];
__device__ float g_VG[512 * 288];
__device__ float g_L[(size_t)512 * 512 * 12];   // logits [n][m][h]
__device__ float g_A[(size_t)512 * 512 * 12];   // attn   [n][m][h]
__device__ float g_F[512 * 2112];               // feats  [n][h*176 + f]

// ---------- projections: out[n][j] = sum_k s[n][k] W[k][j] + b[j] ----------
__global__ void pProj(const float* __restrict__ s, const float* __restrict__ W,
                      const float* __restrict__ b, int ncols, int which)
{
    __shared__ float sr[384];
    const int n = blockIdx.x, j = threadIdx.x;
    for (int i = j; i < 384; i += blockDim.x) sr[i] = s[n * 384 + i];
    __syncthreads();
    if (j < ncols) {
        float acc = b[j];
        for (int k = 0; k < 384; k++) acc += sr[k] * W[(size_t)k * ncols + j];
        float* out = (which == 0) ? g_Q : (which == 1) ? g_K : (which == 2) ? g_V
                   : (which == 3) ? g_QP : (which == 4) ? g_KP : g_VP;
        out[(size_t)n * ncols + j] = acc;
    }
}

// ---------- rigid transform: x_g = R x + t ----------
__global__ void pTrans(const float* __restrict__ trans, const float* __restrict__ rot)
{
    const int n = blockIdx.x, t = threadIdx.x;   // 192 threads
    const float* R = rot + n * 9;
    const float T0 = trans[n * 3], T1 = trans[n * 3 + 1], T2 = trans[n * 3 + 2];
    const float* src; float* dst; int li;
    if (t < 48)      { src = g_QP + n * 144; dst = g_QG + n * 144; li = t; }
    else if (t < 96) { src = g_KP + n * 144; dst = g_KG + n * 144; li = t - 48; }
    else             { src = g_VP + n * 288; dst = g_VG + n * 288; li = t - 96; }
    float p0 = src[li * 3], p1 = src[li * 3 + 1], p2 = src[li * 3 + 2];
    dst[li * 3 + 0] = R[0] * p0 + R[1] * p1 + R[2] * p2 + T0;
    dst[li * 3 + 1] = R[3] * p0 + R[4] * p1 + R[5] * p2 + T1;
    dst[li * 3 + 2] = R[6] * p0 + R[7] * p1 + R[8] * p2 + T2;
}

// ---------- logits: one thread per (n, m) ----------
__global__ void pLogits(const float* __restrict__ z, const float* __restrict__ trans,
                        const float* __restrict__ Wb, const float* __restrict__ bb,
                        const float* __restrict__ de, const float* __restrict__ sl,
                        const float* __restrict__ hw)
{
    __shared__ float q[192], qg[144], ph[36], shw[12], sbb[12];
    const int n = blockIdx.x, m = threadIdx.x;   // 512 threads
    for (int i = m; i < 192; i += 512) q[i]  = g_Q[(size_t)n * 192 + i];
    for (int i = m; i < 144; i += 512) qg[i] = g_QG[(size_t)n * 144 + i];
    if (m < 12) {
        shw[m] = hw[m];
        sbb[m] = bb[m];
        float a = sl[m], b2 = sl[12 + m], c = sl[24 + m];
        float mx = fmaxf(a, fmaxf(b2, c));
        float ea = expf(a - mx), eb = expf(b2 - mx), ec = expf(c - mx);
        float inv = 1.f / (ea + eb + ec);
        ph[m] = ea * inv; ph[12 + m] = eb * inv; ph[24 + m] = ec * inv;
    }
    __syncthreads();

    // pair_bias = z[n,m,:] . Wb + bb
    float pb[12];
    #pragma unroll
    for (int h = 0; h < 12; h++) pb[h] = sbb[h];
    const float* zr = z + ((size_t)n * 512 + m) * 128;
    for (int c = 0; c < 128; c++) {
        float zv = zr[c];
        const float* w = Wb + c * 12;
        #pragma unroll
        for (int h = 0; h < 12; h++) pb[h] += zv * w[h];
    }

    float dx = trans[n * 3]     - trans[m * 3];
    float dy = trans[n * 3 + 1] - trans[m * 3 + 1];
    float dz = trans[n * 3 + 2] - trans[m * 3 + 2];
    float d  = sqrtf(dx * dx + dy * dy + dz * dz);
    // searchsorted(linspace(0,32,65), d, 'left') - 1, clipped
    int bin = min(max((int)ceilf(d * 2.0f) - 1, 0), 63);
    float lo = (d <= 5.0f) ? 1.f : 0.f;
    float me = (d > 5.0f && d <= 15.0f) ? 1.f : 0.f;

    const float* kr = g_K  + (size_t)m * 192;
    const float* kg = g_KG + (size_t)m * 144;
    float* Lp = g_L + ((size_t)n * 512 + m) * 12;
    #pragma unroll
    for (int h = 0; h < 12; h++) {
        float sc = 0.f;
        #pragma unroll
        for (int c = 0; c < 16; c++) sc += q[h * 16 + c] * kr[h * 16 + c];
        float pd = 0.f;
        #pragma unroll
        for (int i = 0; i < 12; i++) {
            float df = qg[h * 12 + i] - kg[h * 12 + i];
            pd += df * df;
        }
        Lp[h] = 0.25f * sc - 0.5f * pd * shw[h] + pb[h]
              + de[bin * 12 + h] + lo * ph[h] + me * ph[12 + h] + ph[24 + h];
    }
}

// ---------- softmax over m for each (n, h) ----------
__global__ void pSoftmax()
{
    __shared__ float red[16];
    const int n = blockIdx.x, h = blockIdx.y;
    const int t = threadIdx.x;   // 512
    float v = g_L[((size_t)n * 512 + t) * 12 + h];
    float mx = v;
    #pragma unroll
    for (int o = 16; o; o >>= 1) mx = fmaxf(mx, __shfl_xor_sync(0xffffffffu, mx, o));
    if ((t & 31) == 0) red[t >> 5] = mx;
    __syncthreads();
    if (t < 16) {
        float r = red[t];
        #pragma unroll
        for (int o = 8; o; o >>= 1) r = fmaxf(r, __shfl_xor_sync(0xffffu, r, o));
        red[t] = r;
    }
    __syncthreads();
    mx = red[0];
    __syncthreads();
    float e = expf(v - mx);
    float ssum = e;
    #pragma unroll
    for (int o = 16; o; o >>= 1) ssum += __shfl_xor_sync(0xffffffffu, ssum, o);
    if ((t & 31) == 0) red[t >> 5] = ssum;
    __syncthreads();
    if (t < 16) {
        float r = red[t];
        #pragma unroll
        for (int o = 8; o; o >>= 1) r += __shfl_xor_sync(0xffffu, r, o);
        red[t] = r;
    }
    __syncthreads();
    g_A[((size_t)n * 512 + t) * 12 + h] = e / red[0];
}

// ---------- apply: out_scalar, out_pts (+inverse frame +norms), pair_feat ----------
__global__ void pApply(const float* __restrict__ z, const float* __restrict__ trans,
                       const float* __restrict__ rot)
{
    __shared__ float at[6144];   // attn[n][m][h]
    __shared__ float zr[128];
    const int n = blockIdx.x, t = threadIdx.x;   // 256
    for (int i = t; i < 6144; i += 256) at[i] = g_A[(size_t)n * 6144 + i];
    __syncthreads();

    // out_scalar[n,h,c]
    if (t < 192) {
        const int h = t / 16, c = t % 16;
        float acc = 0.f;
        for (int m = 0; m < 512; m++) acc += at[m * 12 + h] * g_V[(size_t)m * 192 + t];
        g_F[(size_t)n * 2112 + h * 176 + c] = acc;
    }
    // out_pts_g -> local frame -> pts + norms
    if (t < 96) {
        const int h = t / 8, p = t % 8;
        float a0 = 0.f, a1 = 0.f, a2 = 0.f;
        for (int m = 0; m < 512; m++) {
            float pm = at[m * 12 + h];
            a0 += pm * g_VG[(size_t)m * 288 + t * 3];
            a1 += pm * g_VG[(size_t)m * 288 + t * 3 + 1];
            a2 += pm * g_VG[(size_t)m * 288 + t * 3 + 2];
        }
        a0 -= trans[n * 3]; a1 -= trans[n * 3 + 1]; a2 -= trans[n * 3 + 2];
        const float* R = rot + n * 9;
        float lx = R[0] * a0 + R[3] * a1 + R[6] * a2;   // R^T
        float ly = R[1] * a0 + R[4] * a1 + R[7] * a2;
        float lz = R[2] * a0 + R[5] * a1 + R[8] * a2;
        float* Fh = g_F + (size_t)n * 2112 + h * 176;
        Fh[16 + p * 3]     = lx;
        Fh[16 + p * 3 + 1] = ly;
        Fh[16 + p * 3 + 2] = lz;
        Fh[40 + p]         = sqrtf(lx * lx + ly * ly + lz * lz);
    }
    // pair_feat[n,h,c]: 1536 outputs, 6 per thread, stage z row per m
    float acc[6] = {0.f, 0.f, 0.f, 0.f, 0.f, 0.f};
    int hh[6], cc[6];
    #pragma unroll
    for (int i = 0; i < 6; i++) { int o = t + 256 * i; hh[i] = o / 128; cc[i] = o % 128; }
    for (int m = 0; m < 512; m++) {
        __syncthreads();
        if (t < 128) zr[t] = z[((size_t)n * 512 + m) * 128 + t];
        __syncthreads();
        #pragma unroll
        for (int i = 0; i < 6; i++) acc[i] += at[m * 12 + hh[i]] * zr[cc[i]];
    }
    #pragma unroll
    for (int i = 0; i < 6; i++)
        g_F[(size_t)n * 2112 + hh[i] * 176 + 48 + cc[i]] = acc[i];
}

// ---------- output GEMM: out[n][co] = g_F[n,:] . Wout[:,co] + bout[co] ----------
__global__ void pOut(const float* __restrict__ Wout, const float* __restrict__ bout,
                     float* __restrict__ out)
{
    __shared__ float fr[2112];
    const int n = blockIdx.x, t = threadIdx.x;   // 384
    for (int i = t; i < 2112; i += 384) fr[i] = g_F[(size_t)n * 2112 + i];
    __syncthreads();
    float acc = bout[t];
    for (int k = 0; k < 2112; k++) acc += fr[k] * Wout[(size_t)k * 384 + t];
    out[(size_t)n * 384 + t] = acc;
}

extern "C" void kernel_launch(void* const* d_in, const int* in_sizes, int n_in,
                              void* d_out, int out_size)
{
    const float* s     = (const float*)d_in[0];
    const float* z     = (const float*)d_in[1];
    const float* trans = (const float*)d_in[2];
    const float* rot   = (const float*)d_in[3];
    // d_in[4] = mask (all true; unused)
    const float* Wq  = (const float*)d_in[5];   const float* bq  = (const float*)d_in[6];
    const float* Wk  = (const float*)d_in[7];   const float* bk  = (const float*)d_in[8];
    const float* Wv  = (const float*)d_in[9];   const float* bv  = (const float*)d_in[10];
    const float* Wqp = (const float*)d_in[11];  const float* bqp = (const float*)d_in[12];
    const float* Wkp = (const float*)d_in[13];  const float* bkp = (const float*)d_in[14];
    const float* Wvp = (const float*)d_in[15];  const float* bvp = (const float*)d_in[16];
    const float* Wb  = (const float*)d_in[17];  const float* bb  = (const float*)d_in[18];
    const float* de  = (const float*)d_in[19];
    const float* sl  = (const float*)d_in[20];
    const float* hw  = (const float*)d_in[21];
    const float* Wout = (const float*)d_in[22];
    const float* bout = (const float*)d_in[23];
    float* out = (float*)d_out;

    pProj<<<512, 192>>>(s, Wq,  bq,  192, 0);
    pProj<<<512, 192>>>(s, Wk,  bk,  192, 1);
    pProj<<<512, 192>>>(s, Wv,  bv,  192, 2);
    pProj<<<512, 144>>>(s, Wqp, bqp, 144, 3);
    pProj<<<512, 144>>>(s, Wkp, bkp, 144, 4);
    pProj<<<512, 288>>>(s, Wvp, bvp, 288, 5);
    pTrans<<<512, 192>>>(trans, rot);
    pLogits<<<512, 512>>>(z, trans, Wb, bb, de, sl, hw);
    pSoftmax<<<dim3(512, 12), 512>>>();
    pApply<<<512, 256>>>(z, trans, rot);
    pOut<<<512, 384>>>(Wout, bout, out);
}

// round 8
// speedup vs baseline: 1.7539x; 1.7539x over previous
#include <cuda_runtime.h>
#include <math.h>

// Stage-optimized version derived mechanically from the validated naive r6 kernel.

__device__ float g_Q[512 * 192];
__device__ float g_K[512 * 192];
__device__ float g_V[512 * 192];
__device__ float g_QP[512 * 144];
__device__ float g_KP[512 * 144];
__device__ float g_VP[512 * 288];
__device__ float g_QG[512 * 144];
__device__ float g_KG[512 * 144];
__device__ float g_VG[512 * 288];
__device__ float g_L[(size_t)512 * 512 * 12];   // logits [n][m][h]
__device__ float g_A[(size_t)512 * 512 * 12];   // attn   [n][m][h]
__device__ float g_F[512 * 2112];               // feats  [n][h*176 + f]
__device__ float g_EP[4 * 512 * 384];           // split-K partials

// ---------------- kProj: fused projection GEMM, 512 x 1152, K=384 ----------------
// grid (18, 8), 256 threads, 64x64 tiles, BK=32, 4x4 micro.
__device__ __forceinline__ void segSelW(int c,
    const float* Wq, const float* Wk, const float* Wv,
    const float* Wqp, const float* Wkp, const float* Wvp,
    const float*& W, int& lc, int& sn)
{
    if (c < 192)      { W = Wq;  lc = c;       sn = 192; }
    else if (c < 384) { W = Wk;  lc = c - 192; sn = 192; }
    else if (c < 576) { W = Wv;  lc = c - 384; sn = 192; }
    else if (c < 720) { W = Wqp; lc = c - 576; sn = 144; }
    else if (c < 864) { W = Wkp; lc = c - 720; sn = 144; }
    else              { W = Wvp; lc = c - 864; sn = 288; }
}

__device__ __forceinline__ void segSelO(int c,
    const float* bq, const float* bk, const float* bv,
    const float* bqp, const float* bkp, const float* bvp,
    float*& out, const float*& bia, int& lc, int& sn)
{
    if (c < 192)      { out = g_Q;  bia = bq;  lc = c;       sn = 192; }
    else if (c < 384) { out = g_K;  bia = bk;  lc = c - 192; sn = 192; }
    else if (c < 576) { out = g_V;  bia = bv;  lc = c - 384; sn = 192; }
    else if (c < 720) { out = g_QP; bia = bqp; lc = c - 576; sn = 144; }
    else if (c < 864) { out = g_KP; bia = bkp; lc = c - 720; sn = 144; }
    else              { out = g_VP; bia = bvp; lc = c - 864; sn = 288; }
}

__global__ void __launch_bounds__(256) kProj(
    const float* __restrict__ s,
    const float* __restrict__ Wq,  const float* __restrict__ bq,
    const float* __restrict__ Wk,  const float* __restrict__ bk,
    const float* __restrict__ Wv,  const float* __restrict__ bv,
    const float* __restrict__ Wqp, const float* __restrict__ bqp,
    const float* __restrict__ Wkp, const float* __restrict__ bkp,
    const float* __restrict__ Wvp, const float* __restrict__ bvp)
{
    __shared__ float As[32 * 68];   // [k][row]
    __shared__ float Bs[32 * 68];   // [k][col]
    const int t  = threadIdx.x;
    const int c0 = blockIdx.x * 64;
    const int r0 = blockIdx.y * 64;
    const int tx = t % 16, ty = t / 16;

    float acc[4][4];
    #pragma unroll
    for (int i = 0; i < 4; i++)
        #pragma unroll
        for (int j = 0; j < 4; j++) acc[i][j] = 0.f;

    for (int kt = 0; kt < 384; kt += 32) {
        __syncthreads();
        // As: 64 rows x 32 k, via float4 (512 float4 / 256 thr = 2 each)
        #pragma unroll
        for (int ii = 0; ii < 2; ii++) {
            int i4 = t + 256 * ii;
            int row = i4 >> 3, kq = i4 & 7;
            float4 a = *(const float4*)(s + (size_t)(r0 + row) * 384 + kt + kq * 4);
            As[(kq * 4 + 0) * 68 + row] = a.x;
            As[(kq * 4 + 1) * 68 + row] = a.y;
            As[(kq * 4 + 2) * 68 + row] = a.z;
            As[(kq * 4 + 3) * 68 + row] = a.w;
        }
        // Bs: 32 k x 64 cols, per-element segment decode
        #pragma unroll
        for (int ii = 0; ii < 8; ii++) {
            int i = t + 256 * ii;
            int k = i >> 6, c = i & 63;
            const float* W; int lc, sn;
            segSelW(c0 + c, Wq, Wk, Wv, Wqp, Wkp, Wvp, W, lc, sn);
            Bs[k * 68 + c] = W[(size_t)(kt + k) * sn + lc];
        }
        __syncthreads();
        #pragma unroll
        for (int k = 0; k < 32; k++) {
            float4 a = *(const float4*)&As[k * 68 + ty * 4];
            float4 b = *(const float4*)&Bs[k * 68 + tx * 4];
            float av[4] = {a.x, a.y, a.z, a.w};
            float bw[4] = {b.x, b.y, b.z, b.w};
            #pragma unroll
            for (int i = 0; i < 4; i++)
                #pragma unroll
                for (int j = 0; j < 4; j++) acc[i][j] += av[i] * bw[j];
        }
    }
    // store: the 4-col group never crosses a segment boundary (all boundaries %4==0)
    float* out; const float* bia; int lc, sn;
    segSelO(c0 + tx * 4, bq, bk, bv, bqp, bkp, bvp, out, bia, lc, sn);
    float b0 = bia[lc], b1 = bia[lc + 1], b2 = bia[lc + 2], b3 = bia[lc + 3];
    #pragma unroll
    for (int i = 0; i < 4; i++) {
        int row = r0 + ty * 4 + i;
        float4 v = {acc[i][0] + b0, acc[i][1] + b1, acc[i][2] + b2, acc[i][3] + b3};
        *(float4*)(out + (size_t)row * sn + lc) = v;
    }
}

// ---------------- pTrans: unchanged from validated naive ----------------
__global__ void pTrans(const float* __restrict__ trans, const float* __restrict__ rot)
{
    const int n = blockIdx.x, t = threadIdx.x;   // 192 threads
    const float* R = rot + n * 9;
    const float T0 = trans[n * 3], T1 = trans[n * 3 + 1], T2 = trans[n * 3 + 2];
    const float* src; float* dst; int li;
    if (t < 48)      { src = g_QP + n * 144; dst = g_QG + n * 144; li = t; }
    else if (t < 96) { src = g_KP + n * 144; dst = g_KG + n * 144; li = t - 48; }
    else             { src = g_VP + n * 288; dst = g_VG + n * 288; li = t - 96; }
    float p0 = src[li * 3], p1 = src[li * 3 + 1], p2 = src[li * 3 + 2];
    dst[li * 3 + 0] = R[0] * p0 + R[1] * p1 + R[2] * p2 + T0;
    dst[li * 3 + 1] = R[3] * p0 + R[4] * p1 + R[5] * p2 + T1;
    dst[li * 3 + 2] = R[6] * p0 + R[7] * p1 + R[8] * p2 + T2;
}

// ---------------- pLogits2: naive + smem Wb + float4 z ----------------
__global__ void __launch_bounds__(512) pLogits2(
    const float* __restrict__ z, const float* __restrict__ trans,
    const float* __restrict__ Wb, const float* __restrict__ bb,
    const float* __restrict__ de, const float* __restrict__ sl,
    const float* __restrict__ hw)
{
    __shared__ float q[192], qg[144], ph[36], shw[12], sbb[12], sWb[1536];
    const int n = blockIdx.x, m = threadIdx.x;   // 512 threads
    for (int i = m; i < 192; i += 512) q[i]  = g_Q[(size_t)n * 192 + i];
    for (int i = m; i < 144; i += 512) qg[i] = g_QG[(size_t)n * 144 + i];
    if (m < 12) {
        shw[m] = hw[m];
        sbb[m] = bb[m];
        float a = sl[m], b2 = sl[12 + m], c = sl[24 + m];
        float mx = fmaxf(a, fmaxf(b2, c));
        float ea = expf(a - mx), eb = expf(b2 - mx), ec = expf(c - mx);
        float inv = 1.f / (ea + eb + ec);
        ph[m] = ea * inv; ph[12 + m] = eb * inv; ph[24 + m] = ec * inv;
    }
    for (int i = m; i < 1536; i += 512) sWb[i] = Wb[i];
    __syncthreads();

    float pb[12];
    #pragma unroll
    for (int h = 0; h < 12; h++) pb[h] = sbb[h];
    const float4* zp = (const float4*)(z + ((size_t)n * 512 + m) * 128);
    #pragma unroll 4
    for (int c4 = 0; c4 < 32; c4++) {
        float4 zv = zp[c4];
        const float* w = &sWb[c4 * 48];
        #pragma unroll
        for (int h = 0; h < 12; h++)
            pb[h] += zv.x * w[h] + zv.y * w[12 + h] + zv.z * w[24 + h] + zv.w * w[36 + h];
    }

    float dx = trans[n * 3]     - trans[m * 3];
    float dy = trans[n * 3 + 1] - trans[m * 3 + 1];
    float dz = trans[n * 3 + 2] - trans[m * 3 + 2];
    float d  = sqrtf(dx * dx + dy * dy + dz * dz);
    int bin = min(max((int)ceilf(d * 2.0f) - 1, 0), 63);
    float lo = (d <= 5.0f) ? 1.f : 0.f;
    float me = (d > 5.0f && d <= 15.0f) ? 1.f : 0.f;

    const float* kr = g_K  + (size_t)m * 192;
    const float* kg = g_KG + (size_t)m * 144;
    float* Lp = g_L + ((size_t)n * 512 + m) * 12;
    #pragma unroll
    for (int h = 0; h < 12; h++) {
        float sc = 0.f;
        #pragma unroll
        for (int c = 0; c < 16; c++) sc += q[h * 16 + c] * kr[h * 16 + c];
        float pd = 0.f;
        #pragma unroll
        for (int i = 0; i < 12; i++) {
            float df = qg[h * 12 + i] - kg[h * 12 + i];
            pd += df * df;
        }
        Lp[h] = 0.25f * sc - 0.5f * pd * shw[h] + pb[h]
              + de[bin * 12 + h] + lo * ph[h] + me * ph[12 + h] + ph[24 + h];
    }
}

// ---------------- kSoftA: per-n softmax over m for all 12 heads ----------------
__global__ void __launch_bounds__(384) kSoftA()
{
    __shared__ float sL[6144];
    const int n = blockIdx.x, t = threadIdx.x;   // 384 threads, warp per head
    for (int i = t; i < 6144; i += 384) sL[i] = g_L[(size_t)n * 6144 + i];
    __syncthreads();
    const int h = t >> 5, l = t & 31;
    float mx = -1e30f;
    #pragma unroll
    for (int r = 0; r < 16; r++) mx = fmaxf(mx, sL[(l + 32 * r) * 12 + h]);
    #pragma unroll
    for (int o = 16; o; o >>= 1) mx = fmaxf(mx, __shfl_xor_sync(0xffffffffu, mx, o));
    float ssum = 0.f;
    #pragma unroll
    for (int r = 0; r < 16; r++) ssum += expf(sL[(l + 32 * r) * 12 + h] - mx);
    #pragma unroll
    for (int o = 16; o; o >>= 1) ssum += __shfl_xor_sync(0xffffffffu, ssum, o);
    const float inv = 1.0f / ssum;
    #pragma unroll
    for (int r = 0; r < 16; r++) {
        int m = l + 32 * r;
        g_A[(size_t)n * 6144 + m * 12 + h] = expf(sL[m * 12 + h] - mx) * inv;
    }
}

// ---------------- kApply2: fused apply, z staged in 32-row tiles ----------------
__global__ void __launch_bounds__(384) kApply2(
    const float* __restrict__ z, const float* __restrict__ trans,
    const float* __restrict__ rot)
{
    __shared__ float at[6144];   // attn [m][h]
    __shared__ float zt[4096];   // z tile [32][128]
    const int n = blockIdx.x, t = threadIdx.x;   // 384 threads
    for (int i = t; i < 6144; i += 384) at[i] = g_A[(size_t)n * 6144 + i];

    // pair mapping: h = t/32, cols (t%32)*4 .. +3
    const int hq = t >> 5;
    const int cq = (t & 31) * 4;
    float p0 = 0.f, p1 = 0.f, p2 = 0.f, p3 = 0.f;

    // scalar mapping (t<192): h = t/16, c = t%16 ; pts mapping (192<=t<288)
    const int hs = t / 16;          // valid for t<192
    const int pl = t - 192;         // valid 0..95
    const int hp = pl / 8, pp = pl % 8;
    float as = 0.f, a0 = 0.f, a1 = 0.f, a2 = 0.f;

    for (int mt = 0; mt < 16; mt++) {
        const int m0 = mt * 32;
        __syncthreads();
        // load z tile: 1024 float4 / 384 threads
        for (int i4 = t; i4 < 1024; i4 += 384) {
            int mm = i4 >> 5, c4 = i4 & 31;
            *(float4*)&zt[mm * 128 + c4 * 4] =
                *(const float4*)(z + ((size_t)n * 512 + m0 + mm) * 128 + c4 * 4);
        }
        __syncthreads();
        #pragma unroll 4
        for (int mm = 0; mm < 32; mm++) {
            float pa = at[(m0 + mm) * 12 + hq];
            float4 zz = *(const float4*)&zt[mm * 128 + cq];
            p0 += pa * zz.x; p1 += pa * zz.y; p2 += pa * zz.z; p3 += pa * zz.w;
        }
        if (t < 192) {
            #pragma unroll 4
            for (int mm = 0; mm < 32; mm++)
                as += at[(m0 + mm) * 12 + hs] * g_V[(size_t)(m0 + mm) * 192 + t];
        } else if (t < 288) {
            #pragma unroll 4
            for (int mm = 0; mm < 32; mm++) {
                float pm = at[(m0 + mm) * 12 + hp];
                const float* vg = g_VG + (size_t)(m0 + mm) * 288 + pl * 3;
                a0 += pm * vg[0]; a1 += pm * vg[1]; a2 += pm * vg[2];
            }
        }
    }
    // pair_feat
    {
        float4 v = {p0, p1, p2, p3};
        *(float4*)(g_F + (size_t)n * 2112 + hq * 176 + 48 + cq) = v;
    }
    // out_scalar
    if (t < 192)
        g_F[(size_t)n * 2112 + hs * 176 + (t % 16)] = as;
    // out_pts -> local frame + norms
    if (t >= 192 && t < 288) {
        a0 -= trans[n * 3]; a1 -= trans[n * 3 + 1]; a2 -= trans[n * 3 + 2];
        const float* R = rot + n * 9;
        float lx = R[0] * a0 + R[3] * a1 + R[6] * a2;   // R^T
        float ly = R[1] * a0 + R[4] * a1 + R[7] * a2;
        float lz = R[2] * a0 + R[5] * a1 + R[8] * a2;
        float* Fh = g_F + (size_t)n * 2112 + hp * 176;
        Fh[16 + pp * 3]     = lx;
        Fh[16 + pp * 3 + 1] = ly;
        Fh[16 + pp * 3 + 2] = lz;
        Fh[40 + pp]         = sqrtf(lx * lx + ly * ly + lz * lz);
    }
}

// ---------------- kOut: tiled split-K GEMM 512x384, K=2112 (4 x 528) ----------------
__global__ void __launch_bounds__(256) kOut(const float* __restrict__ Wout)
{
    __shared__ float As[16 * 68];   // [k][row]
    __shared__ float Bs[16 * 68];   // [k][col]
    const int t  = threadIdx.x;
    const int c0 = blockIdx.x * 64;
    const int r0 = blockIdx.y * 64;
    const int k0 = blockIdx.z * 528;
    const int tx = t % 16, ty = t / 16;
    float acc[4][4];
    #pragma unroll
    for (int i = 0; i < 4; i++)
        #pragma unroll
        for (int j = 0; j < 4; j++) acc[i][j] = 0.f;

    for (int kt = 0; kt < 33; kt++) {
        const int kb = k0 + kt * 16;
        __syncthreads();
        #pragma unroll
        for (int ii = 0; ii < 4; ii++) {
            int i = t + 256 * ii;
            int row = i >> 4, k = i & 15;
            As[k * 68 + row] = g_F[(size_t)(r0 + row) * 2112 + kb + k];
        }
        #pragma unroll
        for (int ii = 0; ii < 4; ii++) {
            int i = t + 256 * ii;
            int k = i >> 6, c = i & 63;
            Bs[k * 68 + c] = Wout[(size_t)(kb + k) * 384 + c0 + c];
        }
        __syncthreads();
        #pragma unroll
        for (int k = 0; k < 16; k++) {
            float4 a = *(const float4*)&As[k * 68 + ty * 4];
            float4 b = *(const float4*)&Bs[k * 68 + tx * 4];
            float av[4] = {a.x, a.y, a.z, a.w};
            float bw[4] = {b.x, b.y, b.z, b.w};
            #pragma unroll
            for (int i = 0; i < 4; i++)
                #pragma unroll
                for (int j = 0; j < 4; j++) acc[i][j] += av[i] * bw[j];
        }
    }
    float* Pp = g_EP + (size_t)blockIdx.z * 512 * 384;
    #pragma unroll
    for (int i = 0; i < 4; i++) {
        float4 v = {acc[i][0], acc[i][1], acc[i][2], acc[i][3]};
        *(float4*)(Pp + (size_t)(r0 + ty * 4 + i) * 384 + c0 + tx * 4) = v;
    }
}

__global__ void __launch_bounds__(256) kOutRed(float* __restrict__ out,
                                               const float* __restrict__ bout)
{
    const int e = (blockIdx.x * 256 + threadIdx.x) * 4;
    float4 acc = *(const float4*)(bout + (e % 384));
    #pragma unroll
    for (int zz = 0; zz < 4; zz++) {
        float4 p = *(const float4*)(g_EP + (size_t)zz * 512 * 384 + e);
        acc.x += p.x; acc.y += p.y; acc.z += p.z; acc.w += p.w;
    }
    *(float4*)(out + e) = acc;
}

extern "C" void kernel_launch(void* const* d_in, const int* in_sizes, int n_in,
                              void* d_out, int out_size)
{
    const float* s     = (const float*)d_in[0];
    const float* z     = (const float*)d_in[1];
    const float* trans = (const float*)d_in[2];
    const float* rot   = (const float*)d_in[3];
    // d_in[4] = mask (all true; unused)
    const float* Wq  = (const float*)d_in[5];   const float* bq  = (const float*)d_in[6];
    const float* Wk  = (const float*)d_in[7];   const float* bk  = (const float*)d_in[8];
    const float* Wv  = (const float*)d_in[9];   const float* bv  = (const float*)d_in[10];
    const float* Wqp = (const float*)d_in[11];  const float* bqp = (const float*)d_in[12];
    const float* Wkp = (const float*)d_in[13];  const float* bkp = (const float*)d_in[14];
    const float* Wvp = (const float*)d_in[15];  const float* bvp = (const float*)d_in[16];
    const float* Wb  = (const float*)d_in[17];  const float* bb  = (const float*)d_in[18];
    const float* de  = (const float*)d_in[19];
    const float* sl  = (const float*)d_in[20];
    const float* hw  = (const float*)d_in[21];
    const float* Wout = (const float*)d_in[22];
    const float* bout = (const float*)d_in[23];
    float* out = (float*)d_out;

    kProj<<<dim3(18, 8), 256>>>(s, Wq, bq, Wk, bk, Wv, bv, Wqp, bqp, Wkp, bkp, Wvp, bvp);
    pTrans<<<512, 192>>>(trans, rot);
    pLogits2<<<512, 512>>>(z, trans, Wb, bb, de, sl, hw);
    kSoftA<<<512, 384>>>();
    kApply2<<<512, 384>>>(z, trans, rot);
    kOut<<<dim3(6, 8, 4), 256>>>(Wout);
    kOutRed<<<192, 256>>>(out, bout);
}

// round 9
// speedup vs baseline: 2.0233x; 1.1536x over previous
#include <cuda_runtime.h>
#include <math.h>

__device__ float g_Q[512 * 192];
__device__ float g_K[512 * 192];
__device__ float g_V[512 * 192];
__device__ float g_QP[512 * 144];
__device__ float g_KP[512 * 144];
__device__ float g_VP[512 * 288];
__device__ float g_QG[512 * 144];
__device__ float g_KG[512 * 144];
__device__ float g_VG[512 * 288];
__device__ float g_L[(size_t)512 * 512 * 12];   // logits [n][m][h]
__device__ float g_F[512 * 2112];               // feats  [n][h*176 + f]
__device__ float g_EP[4 * 512 * 384];           // split-K partials

// ---------------- kProj: fused projection GEMM, 512 x 1152, K=384 (validated r7) ----------------
__device__ __forceinline__ void segSelW(int c,
    const float* Wq, const float* Wk, const float* Wv,
    const float* Wqp, const float* Wkp, const float* Wvp,
    const float*& W, int& lc, int& sn)
{
    if (c < 192)      { W = Wq;  lc = c;       sn = 192; }
    else if (c < 384) { W = Wk;  lc = c - 192; sn = 192; }
    else if (c < 576) { W = Wv;  lc = c - 384; sn = 192; }
    else if (c < 720) { W = Wqp; lc = c - 576; sn = 144; }
    else if (c < 864) { W = Wkp; lc = c - 720; sn = 144; }
    else              { W = Wvp; lc = c - 864; sn = 288; }
}

__device__ __forceinline__ void segSelO(int c,
    const float* bq, const float* bk, const float* bv,
    const float* bqp, const float* bkp, const float* bvp,
    float*& out, const float*& bia, int& lc, int& sn)
{
    if (c < 192)      { out = g_Q;  bia = bq;  lc = c;       sn = 192; }
    else if (c < 384) { out = g_K;  bia = bk;  lc = c - 192; sn = 192; }
    else if (c < 576) { out = g_V;  bia = bv;  lc = c - 384; sn = 192; }
    else if (c < 720) { out = g_QP; bia = bqp; lc = c - 576; sn = 144; }
    else if (c < 864) { out = g_KP; bia = bkp; lc = c - 720; sn = 144; }
    else              { out = g_VP; bia = bvp; lc = c - 864; sn = 288; }
}

__global__ void __launch_bounds__(256) kProj(
    const float* __restrict__ s,
    const float* __restrict__ Wq,  const float* __restrict__ bq,
    const float* __restrict__ Wk,  const float* __restrict__ bk,
    const float* __restrict__ Wv,  const float* __restrict__ bv,
    const float* __restrict__ Wqp, const float* __restrict__ bqp,
    const float* __restrict__ Wkp, const float* __restrict__ bkp,
    const float* __restrict__ Wvp, const float* __restrict__ bvp)
{
    __shared__ float As[32 * 68];
    __shared__ float Bs[32 * 68];
    const int t  = threadIdx.x;
    const int c0 = blockIdx.x * 64;
    const int r0 = blockIdx.y * 64;
    const int tx = t % 16, ty = t / 16;

    float acc[4][4];
    #pragma unroll
    for (int i = 0; i < 4; i++)
        #pragma unroll
        for (int j = 0; j < 4; j++) acc[i][j] = 0.f;

    for (int kt = 0; kt < 384; kt += 32) {
        __syncthreads();
        #pragma unroll
        for (int ii = 0; ii < 2; ii++) {
            int i4 = t + 256 * ii;
            int row = i4 >> 3, kq = i4 & 7;
            float4 a = *(const float4*)(s + (size_t)(r0 + row) * 384 + kt + kq * 4);
            As[(kq * 4 + 0) * 68 + row] = a.x;
            As[(kq * 4 + 1) * 68 + row] = a.y;
            As[(kq * 4 + 2) * 68 + row] = a.z;
            As[(kq * 4 + 3) * 68 + row] = a.w;
        }
        #pragma unroll
        for (int ii = 0; ii < 8; ii++) {
            int i = t + 256 * ii;
            int k = i >> 6, c = i & 63;
            const float* W; int lc, sn;
            segSelW(c0 + c, Wq, Wk, Wv, Wqp, Wkp, Wvp, W, lc, sn);
            Bs[k * 68 + c] = W[(size_t)(kt + k) * sn + lc];
        }
        __syncthreads();
        #pragma unroll
        for (int k = 0; k < 32; k++) {
            float4 a = *(const float4*)&As[k * 68 + ty * 4];
            float4 b = *(const float4*)&Bs[k * 68 + tx * 4];
            float av[4] = {a.x, a.y, a.z, a.w};
            float bw[4] = {b.x, b.y, b.z, b.w};
            #pragma unroll
            for (int i = 0; i < 4; i++)
                #pragma unroll
                for (int j = 0; j < 4; j++) acc[i][j] += av[i] * bw[j];
        }
    }
    float* out; const float* bia; int lc, sn;
    segSelO(c0 + tx * 4, bq, bk, bv, bqp, bkp, bvp, out, bia, lc, sn);
    float b0 = bia[lc], b1 = bia[lc + 1], b2 = bia[lc + 2], b3 = bia[lc + 3];
    #pragma unroll
    for (int i = 0; i < 4; i++) {
        int row = r0 + ty * 4 + i;
        float4 v = {acc[i][0] + b0, acc[i][1] + b1, acc[i][2] + b2, acc[i][3] + b3};
        *(float4*)(out + (size_t)row * sn + lc) = v;
    }
}

// ---------------- pTrans (validated) ----------------
__global__ void pTrans(const float* __restrict__ trans, const float* __restrict__ rot)
{
    const int n = blockIdx.x, t = threadIdx.x;   // 192 threads
    const float* R = rot + n * 9;
    const float T0 = trans[n * 3], T1 = trans[n * 3 + 1], T2 = trans[n * 3 + 2];
    const float* src; float* dst; int li;
    if (t < 48)      { src = g_QP + n * 144; dst = g_QG + n * 144; li = t; }
    else if (t < 96) { src = g_KP + n * 144; dst = g_KG + n * 144; li = t - 48; }
    else             { src = g_VP + n * 288; dst = g_VG + n * 288; li = t - 96; }
    float p0 = src[li * 3], p1 = src[li * 3 + 1], p2 = src[li * 3 + 2];
    dst[li * 3 + 0] = R[0] * p0 + R[1] * p1 + R[2] * p2 + T0;
    dst[li * 3 + 1] = R[3] * p0 + R[4] * p1 + R[5] * p2 + T1;
    dst[li * 3 + 2] = R[6] * p0 + R[7] * p1 + R[8] * p2 + T2;
}

// ---------------- pLogits3: 2 query rows per CTA ----------------
__global__ void __launch_bounds__(512) pLogits3(
    const float* __restrict__ z, const float* __restrict__ trans,
    const float* __restrict__ Wb, const float* __restrict__ bb,
    const float* __restrict__ de, const float* __restrict__ sl,
    const float* __restrict__ hw)
{
    __shared__ float q2[384], qg2[288], sWb[1536], ph[36], shw[12], sbb[12];
    const int n0 = blockIdx.x * 2;
    const int m = threadIdx.x;   // 512 threads, one m each
    for (int i = m; i < 384; i += 512) q2[i]  = g_Q[(size_t)(n0 + i / 192) * 192 + i % 192];
    for (int i = m; i < 288; i += 512) qg2[i] = g_QG[(size_t)(n0 + i / 144) * 144 + i % 144];
    for (int i = m; i < 1536; i += 512) sWb[i] = Wb[i];
    if (m < 12) {
        shw[m] = hw[m];
        sbb[m] = bb[m];
        float a = sl[m], b2 = sl[12 + m], c = sl[24 + m];
        float mx = fmaxf(a, fmaxf(b2, c));
        float ea = expf(a - mx), eb = expf(b2 - mx), ec = expf(c - mx);
        float inv = 1.f / (ea + eb + ec);
        ph[m] = ea * inv; ph[12 + m] = eb * inv; ph[24 + m] = ec * inv;
    }
    __syncthreads();

    float pb0[12], pb1[12];
    #pragma unroll
    for (int h = 0; h < 12; h++) { pb0[h] = sbb[h]; pb1[h] = sbb[h]; }
    const float4* zp0 = (const float4*)(z + ((size_t)n0 * 512 + m) * 128);
    const float4* zp1 = (const float4*)(z + ((size_t)(n0 + 1) * 512 + m) * 128);
    #pragma unroll 2
    for (int c4 = 0; c4 < 32; c4++) {
        float4 a = zp0[c4];
        float4 b = zp1[c4];
        const float* w = &sWb[c4 * 48];
        #pragma unroll
        for (int h = 0; h < 12; h++) {
            float w0 = w[h], w1 = w[12 + h], w2 = w[24 + h], w3 = w[36 + h];
            pb0[h] += a.x * w0 + a.y * w1 + a.z * w2 + a.w * w3;
            pb1[h] += b.x * w0 + b.y * w1 + b.z * w2 + b.w * w3;
        }
    }

    const float tmx = trans[m * 3], tmy = trans[m * 3 + 1], tmz = trans[m * 3 + 2];
    float d0, d1;
    {
        float dx = trans[n0 * 3]     - tmx;
        float dy = trans[n0 * 3 + 1] - tmy;
        float dz = trans[n0 * 3 + 2] - tmz;
        d0 = sqrtf(dx * dx + dy * dy + dz * dz);
        dx = trans[(n0 + 1) * 3]     - tmx;
        dy = trans[(n0 + 1) * 3 + 1] - tmy;
        dz = trans[(n0 + 1) * 3 + 2] - tmz;
        d1 = sqrtf(dx * dx + dy * dy + dz * dz);
    }
    int bin0 = min(max((int)ceilf(d0 * 2.0f) - 1, 0), 63);
    int bin1 = min(max((int)ceilf(d1 * 2.0f) - 1, 0), 63);
    float lo0 = (d0 <= 5.0f) ? 1.f : 0.f;
    float me0 = (d0 > 5.0f && d0 <= 15.0f) ? 1.f : 0.f;
    float lo1 = (d1 <= 5.0f) ? 1.f : 0.f;
    float me1 = (d1 > 5.0f && d1 <= 15.0f) ? 1.f : 0.f;

    const float* kr = g_K  + (size_t)m * 192;
    const float* kg = g_KG + (size_t)m * 144;
    float* Lp0 = g_L + ((size_t)n0 * 512 + m) * 12;
    float* Lp1 = g_L + ((size_t)(n0 + 1) * 512 + m) * 12;
    #pragma unroll
    for (int h = 0; h < 12; h++) {
        float sc0 = 0.f, sc1 = 0.f;
        #pragma unroll
        for (int c = 0; c < 16; c++) {
            float kv = kr[h * 16 + c];
            sc0 += q2[h * 16 + c] * kv;
            sc1 += q2[192 + h * 16 + c] * kv;
        }
        float pd0 = 0.f, pd1 = 0.f;
        #pragma unroll
        for (int i = 0; i < 12; i++) {
            float kv = kg[h * 12 + i];
            float f0 = qg2[h * 12 + i] - kv;
            float f1 = qg2[144 + h * 12 + i] - kv;
            pd0 += f0 * f0;
            pd1 += f1 * f1;
        }
        Lp0[h] = 0.25f * sc0 - 0.5f * pd0 * shw[h] + pb0[h]
               + de[bin0 * 12 + h] + lo0 * ph[h] + me0 * ph[12 + h] + ph[24 + h];
        Lp1[h] = 0.25f * sc1 - 0.5f * pd1 * shw[h] + pb1[h]
               + de[bin1 * 12 + h] + lo1 * ph[h] + me1 * ph[12 + h] + ph[24 + h];
    }
}

// ---------------- kApply3: fused softmax + apply ----------------
// 512 threads: t<128 pair_feat (4 warps x 3 heads x 4 cols), 128..319 scalar,
// 320..415 pts, rest assist staging.
__global__ void __launch_bounds__(512) kApply3(
    const float* __restrict__ z, const float* __restrict__ trans,
    const float* __restrict__ rot)
{
    __shared__ float at[6144];   // logits -> probs [m][12]
    __shared__ float zt[4096];   // z tile [32][128]
    const int n = blockIdx.x, t = threadIdx.x;
    for (int i = t; i < 6144; i += 512) at[i] = g_L[(size_t)n * 6144 + i];
    __syncthreads();

    // in-place softmax, warp per head (validated kSoftA math)
    const int wid = t >> 5, lane = t & 31;
    if (wid < 12) {
        const int h = wid;
        float mx = -1e30f;
        #pragma unroll
        for (int r = 0; r < 16; r++) mx = fmaxf(mx, at[(lane + 32 * r) * 12 + h]);
        #pragma unroll
        for (int o = 16; o; o >>= 1) mx = fmaxf(mx, __shfl_xor_sync(0xffffffffu, mx, o));
        float ssum = 0.f;
        #pragma unroll
        for (int r = 0; r < 16; r++) ssum += expf(at[(lane + 32 * r) * 12 + h] - mx);
        #pragma unroll
        for (int o = 16; o; o >>= 1) ssum += __shfl_xor_sync(0xffffffffu, ssum, o);
        const float inv = 1.0f / ssum;
        #pragma unroll
        for (int r = 0; r < 16; r++) {
            int mm = lane + 32 * r;
            at[mm * 12 + h] = expf(at[mm * 12 + h] - mx) * inv;
        }
    }
    __syncthreads();

    // role setup
    const int cq = (t & 31) * 4;        // pair: 4 cols
    const int hb = (t >> 5) * 3;        // pair: head base (warps 0-3)
    float pacc[3][4];
    #pragma unroll
    for (int i = 0; i < 3; i++)
        #pragma unroll
        for (int j = 0; j < 4; j++) pacc[i][j] = 0.f;
    const int js = t - 128;             // scalar: 0..191 -> h=js/16, c=js%16
    float sacc = 0.f;
    const int jp = t - 320;             // pts: 0..95 -> hp=jp/8, pp=jp%8
    float a0 = 0.f, a1 = 0.f, a2 = 0.f;

    for (int mt = 0; mt < 16; mt++) {
        const int m0 = mt * 32;
        __syncthreads();
        for (int i4 = t; i4 < 1024; i4 += 512) {
            int mm = i4 >> 5, c4 = i4 & 31;
            *(float4*)&zt[mm * 128 + c4 * 4] =
                *(const float4*)(z + ((size_t)n * 512 + m0 + mm) * 128 + c4 * 4);
        }
        __syncthreads();
        if (t < 128) {
            #pragma unroll 4
            for (int mm = 0; mm < 32; mm++) {
                float4 zz = *(const float4*)&zt[mm * 128 + cq];
                const float* pm = &at[(m0 + mm) * 12 + hb];
                #pragma unroll
                for (int hh = 0; hh < 3; hh++) {
                    float p = pm[hh];
                    pacc[hh][0] += p * zz.x; pacc[hh][1] += p * zz.y;
                    pacc[hh][2] += p * zz.z; pacc[hh][3] += p * zz.w;
                }
            }
        } else if (t < 320) {
            const int hs = js / 16;
            #pragma unroll 4
            for (int mm = 0; mm < 32; mm++)
                sacc += at[(m0 + mm) * 12 + hs] * g_V[(size_t)(m0 + mm) * 192 + js];
        } else if (t < 416) {
            const int hp = jp / 8;
            #pragma unroll 4
            for (int mm = 0; mm < 32; mm++) {
                float pm = at[(m0 + mm) * 12 + hp];
                const float* vg = g_VG + (size_t)(m0 + mm) * 288 + jp * 3;
                a0 += pm * vg[0]; a1 += pm * vg[1]; a2 += pm * vg[2];
            }
        }
    }

    if (t < 128) {
        #pragma unroll
        for (int hh = 0; hh < 3; hh++) {
            float4 v = {pacc[hh][0], pacc[hh][1], pacc[hh][2], pacc[hh][3]};
            *(float4*)(g_F + (size_t)n * 2112 + (hb + hh) * 176 + 48 + cq) = v;
        }
    } else if (t < 320) {
        g_F[(size_t)n * 2112 + (js / 16) * 176 + (js % 16)] = sacc;
    } else if (t < 416) {
        const int hp = jp / 8, pp = jp % 8;
        a0 -= trans[n * 3]; a1 -= trans[n * 3 + 1]; a2 -= trans[n * 3 + 2];
        const float* R = rot + n * 9;
        float lx = R[0] * a0 + R[3] * a1 + R[6] * a2;   // R^T
        float ly = R[1] * a0 + R[4] * a1 + R[7] * a2;
        float lz = R[2] * a0 + R[5] * a1 + R[8] * a2;
        float* Fh = g_F + (size_t)n * 2112 + hp * 176;
        Fh[16 + pp * 3]     = lx;
        Fh[16 + pp * 3 + 1] = ly;
        Fh[16 + pp * 3 + 2] = lz;
        Fh[40 + pp]         = sqrtf(lx * lx + ly * ly + lz * lz);
    }
}

// ---------------- kOut: tiled split-K GEMM 512x384, K=2112 (validated r7) ----------------
__global__ void __launch_bounds__(256) kOut(const float* __restrict__ Wout)
{
    __shared__ float As[16 * 68];
    __shared__ float Bs[16 * 68];
    const int t  = threadIdx.x;
    const int c0 = blockIdx.x * 64;
    const int r0 = blockIdx.y * 64;
    const int k0 = blockIdx.z * 528;
    const int tx = t % 16, ty = t / 16;
    float acc[4][4];
    #pragma unroll
    for (int i = 0; i < 4; i++)
        #pragma unroll
        for (int j = 0; j < 4; j++) acc[i][j] = 0.f;

    for (int kt = 0; kt < 33; kt++) {
        const int kb = k0 + kt * 16;
        __syncthreads();
        #pragma unroll
        for (int ii = 0; ii < 4; ii++) {
            int i = t + 256 * ii;
            int row = i >> 4, k = i & 15;
            As[k * 68 + row] = g_F[(size_t)(r0 + row) * 2112 + kb + k];
        }
        #pragma unroll
        for (int ii = 0; ii < 4; ii++) {
            int i = t + 256 * ii;
            int k = i >> 6, c = i & 63;
            Bs[k * 68 + c] = Wout[(size_t)(kb + k) * 384 + c0 + c];
        }
        __syncthreads();
        #pragma unroll
        for (int k = 0; k < 16; k++) {
            float4 a = *(const float4*)&As[k * 68 + ty * 4];
            float4 b = *(const float4*)&Bs[k * 68 + tx * 4];
            float av[4] = {a.x, a.y, a.z, a.w};
            float bw[4] = {b.x, b.y, b.z, b.w};
            #pragma unroll
            for (int i = 0; i < 4; i++)
                #pragma unroll
                for (int j = 0; j < 4; j++) acc[i][j] += av[i] * bw[j];
        }
    }
    float* Pp = g_EP + (size_t)blockIdx.z * 512 * 384;
    #pragma unroll
    for (int i = 0; i < 4; i++) {
        float4 v = {acc[i][0], acc[i][1], acc[i][2], acc[i][3]};
        *(float4*)(Pp + (size_t)(r0 + ty * 4 + i) * 384 + c0 + tx * 4) = v;
    }
}

__global__ void __launch_bounds__(256) kOutRed(float* __restrict__ out,
                                               const float* __restrict__ bout)
{
    const int e = (blockIdx.x * 256 + threadIdx.x) * 4;
    float4 acc = *(const float4*)(bout + (e % 384));
    #pragma unroll
    for (int zz = 0; zz < 4; zz++) {
        float4 p = *(const float4*)(g_EP + (size_t)zz * 512 * 384 + e);
        acc.x += p.x; acc.y += p.y; acc.z += p.z; acc.w += p.w;
    }
    *(float4*)(out + e) = acc;
}

extern "C" void kernel_launch(void* const* d_in, const int* in_sizes, int n_in,
                              void* d_out, int out_size)
{
    const float* s     = (const float*)d_in[0];
    const float* z     = (const float*)d_in[1];
    const float* trans = (const float*)d_in[2];
    const float* rot   = (const float*)d_in[3];
    // d_in[4] = mask (all true; unused)
    const float* Wq  = (const float*)d_in[5];   const float* bq  = (const float*)d_in[6];
    const float* Wk  = (const float*)d_in[7];   const float* bk  = (const float*)d_in[8];
    const float* Wv  = (const float*)d_in[9];   const float* bv  = (const float*)d_in[10];
    const float* Wqp = (const float*)d_in[11];  const float* bqp = (const float*)d_in[12];
    const float* Wkp = (const float*)d_in[13];  const float* bkp = (const float*)d_in[14];
    const float* Wvp = (const float*)d_in[15];  const float* bvp = (const float*)d_in[16];
    const float* Wb  = (const float*)d_in[17];  const float* bb  = (const float*)d_in[18];
    const float* de  = (const float*)d_in[19];
    const float* sl  = (const float*)d_in[20];
    const float* hw  = (const float*)d_in[21];
    const float* Wout = (const float*)d_in[22];
    const float* bout = (const float*)d_in[23];
    float* out = (float*)d_out;

    kProj<<<dim3(18, 8), 256>>>(s, Wq, bq, Wk, bk, Wv, bv, Wqp, bqp, Wkp, bkp, Wvp, bvp);
    pTrans<<<512, 192>>>(trans, rot);
    pLogits3<<<256, 512>>>(z, trans, Wb, bb, de, sl, hw);
    kApply3<<<512, 512>>>(z, trans, rot);
    kOut<<<dim3(6, 8, 4), 256>>>(Wout);
    kOutRed<<<192, 256>>>(out, bout);
}